// round 1
// baseline (speedup 1.0000x reference)
#include <cuda_runtime.h>

#define DIM 64
#define N_NODES_MAX 100000

// Scratch: accumulator for per-node feature sums and degree counts.
__device__ float g_acc[(size_t)N_NODES_MAX * DIM];
__device__ float g_deg[N_NODES_MAX];

// ---------------------------------------------------------------------------
// Kernel 0: zero the scratch buffers (grid-stride, float4 stores).
// ---------------------------------------------------------------------------
__global__ void zero_kernel(int acc_quads, int deg_quads) {
    int i = blockIdx.x * blockDim.x + threadIdx.x;
    int stride = gridDim.x * blockDim.x;
    float4 z = make_float4(0.f, 0.f, 0.f, 0.f);
    float4* pa = reinterpret_cast<float4*>(g_acc);
    for (int j = i; j < acc_quads; j += stride) pa[j] = z;
    float4* pd = reinterpret_cast<float4*>(g_deg);
    for (int j = i; j < deg_quads; j += stride) pd[j] = z;
}

// ---------------------------------------------------------------------------
// Kernel 1: edge scatter. 16 threads per edge; each thread moves one float4
// of the 64-float feature row via a vectorized no-return reduction
// (red.global.add.v4.f32, sm_90+). Lane group [e*16 .. e*16+15] reads the
// source row as two coalesced 128B lines.
// ---------------------------------------------------------------------------
__global__ void scatter_kernel(const float* __restrict__ x,
                               const int* __restrict__ src,
                               const int* __restrict__ dst,
                               int nEdges) {
    long long idx = (long long)blockIdx.x * blockDim.x + threadIdx.x;
    long long total = (long long)nEdges * 16;
    if (idx >= total) return;
    int e = (int)(idx >> 4);
    int c = (int)(idx & 15);
    int s = __ldg(&src[e]);
    int d = __ldg(&dst[e]);

    float4 v = reinterpret_cast<const float4*>(x + (size_t)s * DIM)[c];
    float* p = g_acc + (size_t)d * DIM + c * 4;
    asm volatile("red.global.add.v4.f32 [%0], {%1, %2, %3, %4};"
                 :: "l"(p), "f"(v.x), "f"(v.y), "f"(v.z), "f"(v.w)
                 : "memory");
    if (c == 0) {
        atomicAdd(g_deg + d, 1.0f);
    }
}

// ---------------------------------------------------------------------------
// Kernel 2: mean-normalize + linear (h @ W^T + b), fused.
// Block = 256 threads handling a 64-node x 64-col output tile.
// h tile (scaled by 1/max(deg,1)) staged transposed in smem as sh[k][node];
// W staged transposed as sW[k][col]. Each thread computes a 4x4 register
// tile with float4 smem loads (rows padded to 68 floats -> 272B, 16B-aligned,
// odd-ish bank stride).
// ---------------------------------------------------------------------------
__global__ __launch_bounds__(256) void agg_linear_kernel(
    const float* __restrict__ W, const float* __restrict__ b,
    float* __restrict__ out, int nNodes) {
    __shared__ float sW[DIM][68];
    __shared__ float sh[DIM][68];
    int tid = threadIdx.x;

    // Load W transposed: sW[k][j] = W[j*64 + k]
    for (int i = tid; i < DIM * DIM; i += 256) {
        int j = i >> 6;
        int k = i & 63;
        sW[k][j] = W[i];
    }

    int n0 = blockIdx.x * 64;

    // Load h tile (64 nodes x 64 dims), normalized by degree, transposed.
    #pragma unroll
    for (int r = 0; r < 16; ++r) {
        int flat = r * 256 + tid;
        int nl = flat >> 6;   // local node 0..63
        int k  = flat & 63;   // feature dim
        int n = n0 + nl;
        float v = 0.f;
        if (n < nNodes) {
            float invd = 1.0f / fmaxf(g_deg[n], 1.0f);
            v = g_acc[(size_t)n * DIM + k] * invd;
        }
        sh[k][nl] = v;
    }
    __syncthreads();

    int tx = tid & 15;   // col group (16 groups of 4 cols)
    int ty = tid >> 4;   // node group (16 groups of 4 nodes)
    int jc  = tx * 4;
    int nl0 = ty * 4;

    float accum[4][4];
    float4 bb = *reinterpret_cast<const float4*>(b + jc);
    #pragma unroll
    for (int a = 0; a < 4; ++a) {
        accum[a][0] = bb.x; accum[a][1] = bb.y;
        accum[a][2] = bb.z; accum[a][3] = bb.w;
    }

    #pragma unroll
    for (int k = 0; k < DIM; ++k) {
        float4 hv = *reinterpret_cast<const float4*>(&sh[k][nl0]);
        float4 wv = *reinterpret_cast<const float4*>(&sW[k][jc]);
        float ha[4] = {hv.x, hv.y, hv.z, hv.w};
        float wa[4] = {wv.x, wv.y, wv.z, wv.w};
        #pragma unroll
        for (int a = 0; a < 4; ++a) {
            #pragma unroll
            for (int c2 = 0; c2 < 4; ++c2) {
                accum[a][c2] += ha[a] * wa[c2];
            }
        }
    }

    #pragma unroll
    for (int a = 0; a < 4; ++a) {
        int n = n0 + nl0 + a;
        if (n < nNodes) {
            float4 o = make_float4(accum[a][0], accum[a][1],
                                   accum[a][2], accum[a][3]);
            *reinterpret_cast<float4*>(out + (size_t)n * DIM + jc) = o;
        }
    }
}

// ---------------------------------------------------------------------------
// Launch. Inputs (metadata order): x [N*64 f32], src [E i32], dst [E i32],
// W [64*64 f32], b [64 f32]. Output: [N*64 f32].
// ---------------------------------------------------------------------------
extern "C" void kernel_launch(void* const* d_in, const int* in_sizes, int n_in,
                              void* d_out, int out_size) {
    const float* x   = (const float*)d_in[0];
    const int*   src = (const int*)d_in[1];
    const int*   dst = (const int*)d_in[2];
    const float* W   = (const float*)d_in[3];
    const float* b   = (const float*)d_in[4];
    float* out = (float*)d_out;

    int nNodes = in_sizes[0] / DIM;
    int nEdges = in_sizes[1];

    int acc_quads = nNodes * (DIM / 4);
    int deg_quads = (nNodes + 3) / 4;
    zero_kernel<<<2048, 256>>>(acc_quads, deg_quads);

    long long total = (long long)nEdges * 16;
    int sblocks = (int)((total + 255) / 256);
    scatter_kernel<<<sblocks, 256>>>(x, src, dst, nEdges);

    int ablocks = (nNodes + 63) / 64;
    agg_linear_kernel<<<ablocks, 256>>>(W, b, out, nNodes);
}

// round 2
// speedup vs baseline: 1.2221x; 1.2221x over previous
#include <cuda_runtime.h>

#define DIM 64
#define MAXN 100000
#define MAXE 1200000

// ---------------------------------------------------------------------------
// Scratch (static device globals; no allocation).
// ---------------------------------------------------------------------------
__device__ int   g_deg[MAXN];
__device__ int   g_off[MAXN + 1];
__device__ int   g_cur[MAXN];
__device__ int   g_ssrc[MAXE];
__device__ float g_h[(size_t)MAXN * DIM];   // normalized mean features
__device__ int   g_bsum[128];

// ---------------------------------------------------------------------------
// K0: zero the degree counters.
// ---------------------------------------------------------------------------
__global__ void k_zero_deg(int n) {
    int i = blockIdx.x * blockDim.x + threadIdx.x;
    if (i < n) g_deg[i] = 0;
}

// ---------------------------------------------------------------------------
// K1: histogram of destination degrees (int REDG, spread addresses).
// ---------------------------------------------------------------------------
__global__ void k_hist(const int* __restrict__ dst, int nE) {
    int i = blockIdx.x * blockDim.x + threadIdx.x;
    if (i < nE) atomicAdd(&g_deg[dst[i]], 1);
}

// ---------------------------------------------------------------------------
// K2a: per-1024-block inclusive scan of g_deg -> g_off (inclusive partials),
//      block totals -> g_bsum.
// ---------------------------------------------------------------------------
__global__ __launch_bounds__(1024) void k_scan1(int n) {
    __shared__ int sm[1024];
    int tid = threadIdx.x;
    int gid = blockIdx.x * 1024 + tid;
    int v = (gid < n) ? g_deg[gid] : 0;
    sm[tid] = v;
    __syncthreads();
    #pragma unroll
    for (int d = 1; d < 1024; d <<= 1) {
        int t = (tid >= d) ? sm[tid - d] : 0;
        __syncthreads();
        sm[tid] += t;
        __syncthreads();
    }
    if (gid < n) g_off[gid] = sm[tid];          // inclusive partial
    if (tid == 1023) g_bsum[blockIdx.x] = sm[1023];
}

// ---------------------------------------------------------------------------
// K2b: single-block inclusive scan of the <=128 block sums.
// ---------------------------------------------------------------------------
__global__ __launch_bounds__(128) void k_scan2(int nblk) {
    __shared__ int sm[128];
    int t = threadIdx.x;
    int v = (t < nblk) ? g_bsum[t] : 0;
    sm[t] = v;
    __syncthreads();
    #pragma unroll
    for (int d = 1; d < 128; d <<= 1) {
        int u = (t >= d) ? sm[t - d] : 0;
        __syncthreads();
        sm[t] += u;
        __syncthreads();
    }
    if (t < nblk) g_bsum[t] = sm[t];
}

// ---------------------------------------------------------------------------
// K2c: finalize exclusive offsets; init fill cursors; set sentinel.
// ---------------------------------------------------------------------------
__global__ __launch_bounds__(1024) void k_scan3(int n, int nE) {
    int gid = blockIdx.x * 1024 + threadIdx.x;
    if (gid < n) {
        int base = (blockIdx.x > 0) ? g_bsum[blockIdx.x - 1] : 0;
        int ex = g_off[gid] - g_deg[gid] + base;   // exclusive offset
        g_off[gid] = ex;
        g_cur[gid] = ex;
    }
    if (gid == 0) g_off[n] = nE;
}

// ---------------------------------------------------------------------------
// K3: bucket-fill sorted source indices by destination.
// ---------------------------------------------------------------------------
__global__ void k_fill(const int* __restrict__ src,
                       const int* __restrict__ dst, int nE) {
    int i = blockIdx.x * blockDim.x + threadIdx.x;
    if (i < nE) {
        int d = dst[i];
        int pos = atomicAdd(&g_cur[d], 1);
        g_ssrc[pos] = src[i];
    }
}

// ---------------------------------------------------------------------------
// K4: atomic-free aggregation. One 16-lane group per node; each lane owns
// 4 feature floats (float4). Gathers source rows as 256B coalesced reads
// (L2-resident x), accumulates in registers, writes normalized mean.
// ---------------------------------------------------------------------------
__global__ __launch_bounds__(256) void k_agg(const float* __restrict__ x, int n) {
    int node = (blockIdx.x * blockDim.x + threadIdx.x) >> 4;
    int l = threadIdx.x & 15;
    unsigned mask = 0xFFFFu << (threadIdx.x & 16);   // own half-warp only
    if (node >= n) return;

    int begin = g_off[node];
    int end   = g_off[node + 1];
    float4 acc = make_float4(0.f, 0.f, 0.f, 0.f);

    for (int base = begin; base < end; base += 16) {
        int m = min(16, end - base);
        int s = (l < m) ? g_ssrc[base + l] : 0;
        int k = 0;
        for (; k + 4 <= m; k += 4) {
            int s0 = __shfl_sync(mask, s, k + 0, 16);
            int s1 = __shfl_sync(mask, s, k + 1, 16);
            int s2 = __shfl_sync(mask, s, k + 2, 16);
            int s3 = __shfl_sync(mask, s, k + 3, 16);
            float4 v0 = *reinterpret_cast<const float4*>(x + (size_t)s0 * DIM + l * 4);
            float4 v1 = *reinterpret_cast<const float4*>(x + (size_t)s1 * DIM + l * 4);
            float4 v2 = *reinterpret_cast<const float4*>(x + (size_t)s2 * DIM + l * 4);
            float4 v3 = *reinterpret_cast<const float4*>(x + (size_t)s3 * DIM + l * 4);
            acc.x += (v0.x + v1.x) + (v2.x + v3.x);
            acc.y += (v0.y + v1.y) + (v2.y + v3.y);
            acc.z += (v0.z + v1.z) + (v2.z + v3.z);
            acc.w += (v0.w + v1.w) + (v2.w + v3.w);
        }
        for (; k < m; ++k) {
            int s0 = __shfl_sync(mask, s, k, 16);
            float4 v0 = *reinterpret_cast<const float4*>(x + (size_t)s0 * DIM + l * 4);
            acc.x += v0.x; acc.y += v0.y; acc.z += v0.z; acc.w += v0.w;
        }
    }

    float invd = 1.0f / fmaxf((float)(end - begin), 1.0f);
    acc.x *= invd; acc.y *= invd; acc.z *= invd; acc.w *= invd;
    *reinterpret_cast<float4*>(g_h + (size_t)node * DIM + l * 4) = acc;
}

// ---------------------------------------------------------------------------
// K5: linear layer out = h @ W^T + b. 64-node x 64-col tile per 256-thread
// block, 4x4 register tiles, float4 smem loads.
// ---------------------------------------------------------------------------
__global__ __launch_bounds__(256) void k_gemm(
    const float* __restrict__ W, const float* __restrict__ b,
    float* __restrict__ out, int nNodes) {
    __shared__ float sW[DIM][68];
    __shared__ float sh[DIM][68];
    int tid = threadIdx.x;

    for (int i = tid; i < DIM * DIM; i += 256) {
        int j = i >> 6;
        int k = i & 63;
        sW[k][j] = W[i];   // transposed: sW[k][col]
    }

    int n0 = blockIdx.x * 64;
    #pragma unroll
    for (int r = 0; r < 16; ++r) {
        int flat = r * 256 + tid;
        int nl = flat >> 6;
        int k  = flat & 63;
        int n = n0 + nl;
        float v = 0.f;
        if (n < nNodes) v = g_h[(size_t)n * DIM + k];
        sh[k][nl] = v;
    }
    __syncthreads();

    int tx = tid & 15;
    int ty = tid >> 4;
    int jc  = tx * 4;
    int nl0 = ty * 4;

    float accum[4][4];
    float4 bb = *reinterpret_cast<const float4*>(b + jc);
    #pragma unroll
    for (int a = 0; a < 4; ++a) {
        accum[a][0] = bb.x; accum[a][1] = bb.y;
        accum[a][2] = bb.z; accum[a][3] = bb.w;
    }

    #pragma unroll
    for (int k = 0; k < DIM; ++k) {
        float4 hv = *reinterpret_cast<const float4*>(&sh[k][nl0]);
        float4 wv = *reinterpret_cast<const float4*>(&sW[k][jc]);
        float ha[4] = {hv.x, hv.y, hv.z, hv.w};
        float wa[4] = {wv.x, wv.y, wv.z, wv.w};
        #pragma unroll
        for (int a = 0; a < 4; ++a)
            #pragma unroll
            for (int c2 = 0; c2 < 4; ++c2)
                accum[a][c2] += ha[a] * wa[c2];
    }

    #pragma unroll
    for (int a = 0; a < 4; ++a) {
        int n = n0 + nl0 + a;
        if (n < nNodes) {
            float4 o = make_float4(accum[a][0], accum[a][1],
                                   accum[a][2], accum[a][3]);
            *reinterpret_cast<float4*>(out + (size_t)n * DIM + jc) = o;
        }
    }
}

// ---------------------------------------------------------------------------
// Launch. Inputs: x [N*64 f32], src [E i32], dst [E i32], W [64*64 f32],
// b [64 f32]. Output: [N*64 f32].
// ---------------------------------------------------------------------------
extern "C" void kernel_launch(void* const* d_in, const int* in_sizes, int n_in,
                              void* d_out, int out_size) {
    const float* x   = (const float*)d_in[0];
    const int*   src = (const int*)d_in[1];
    const int*   dst = (const int*)d_in[2];
    const float* W   = (const float*)d_in[3];
    const float* b   = (const float*)d_in[4];
    float* out = (float*)d_out;

    int nNodes = in_sizes[0] / DIM;
    int nEdges = in_sizes[1];

    int nblkScan = (nNodes + 1023) / 1024;          // 98 for 100k
    int eBlocks  = (nEdges + 255) / 256;

    k_zero_deg<<<(nNodes + 255) / 256, 256>>>(nNodes);
    k_hist<<<eBlocks, 256>>>(dst, nEdges);
    k_scan1<<<nblkScan, 1024>>>(nNodes);
    k_scan2<<<1, 128>>>(nblkScan);
    k_scan3<<<nblkScan, 1024>>>(nNodes, nEdges);
    k_fill<<<eBlocks, 256>>>(src, dst, nEdges);

    int aggBlocks = (nNodes * 16 + 255) / 256;      // 16 lanes per node
    k_agg<<<aggBlocks, 256>>>(x, nNodes);

    int gemmBlocks = (nNodes + 63) / 64;
    k_gemm<<<gemmBlocks, 256>>>(W, b, out, nNodes);
}